// round 1
// baseline (speedup 1.0000x reference)
#include <cuda_runtime.h>
#include <cuda_bf16.h>

#define NN 10000
#define NAG 5000
#define EE 160000
#define ET 170000   /* EE + NN self-loops */
#define HH 8
#define CC 128
#define HC 1024     /* HH*CC */
#define COUT 8

// ---------------- scratch (device globals; no allocation allowed) ----------------
__device__ __align__(16) float g_xl[NN * HC];
__device__ __align__(16) float g_xr[NN * HC];
__device__ __align__(16) float g_ea[ET * HH];
__device__ __align__(16) float g_h1[NN * CC];
__device__ __align__(16) float g_h2[NN * CC];
__device__ int g_deg[NN];
__device__ int g_wp[NN];
__device__ int g_off[NN + 1];
__device__ int g_csr[ET];
__device__ int g_rows[NAG];

// ---------------- CSR build ----------------
__global__ void k_zero2(int* a, int* b, int n) {
    int i = blockIdx.x * blockDim.x + threadIdx.x;
    if (i < n) { a[i] = 0; b[i] = 0; }
}

__global__ void k_count(const int* __restrict__ ei, int* __restrict__ deg) {
    int e = blockIdx.x * blockDim.x + threadIdx.x;
    if (e >= ET) return;
    int dst = (e < EE) ? ei[EE + e] : (e - EE);
    atomicAdd(&deg[dst], 1);
}

__global__ void k_scan(const int* __restrict__ deg, int* __restrict__ off) {
    __shared__ int s[1024];
    int carry = 0;
    for (int base = 0; base < NN; base += 1024) {
        int i = base + threadIdx.x;
        int v = (i < NN) ? deg[i] : 0;
        s[threadIdx.x] = v;
        __syncthreads();
        for (int d = 1; d < 1024; d <<= 1) {
            int t = (threadIdx.x >= d) ? s[threadIdx.x - d] : 0;
            __syncthreads();
            s[threadIdx.x] += t;
            __syncthreads();
        }
        if (i < NN) off[i] = carry + s[threadIdx.x] - v;
        carry += s[1023];
        __syncthreads();
    }
    if (threadIdx.x == 0) off[NN] = carry;
}

__global__ void k_fill(const int* __restrict__ ei, const int* __restrict__ off,
                       int* __restrict__ wp, int* __restrict__ csr) {
    int e = blockIdx.x * blockDim.x + threadIdx.x;
    if (e >= ET) return;
    int src, dst;
    if (e < EE) { src = ei[e]; dst = ei[EE + e]; }
    else        { src = e - EE; dst = src; }
    int p = off[dst] + atomicAdd(&wp[dst], 1);
    csr[p] = src;
}

// Drone row gather list: indices (in order) of nodes with x[:,15] < 0
__global__ void k_rows(const float* __restrict__ x, int* __restrict__ rows) {
    __shared__ int s[1024];
    int carry = 0;
    for (int base = 0; base < NN; base += 1024) {
        int i = base + threadIdx.x;
        int v = (i < NN && x[i * 16 + 15] < 0.f) ? 1 : 0;
        s[threadIdx.x] = v;
        __syncthreads();
        for (int d = 1; d < 1024; d <<= 1) {
            int t = (threadIdx.x >= d) ? s[threadIdx.x - d] : 0;
            __syncthreads();
            s[threadIdx.x] += t;
            __syncthreads();
        }
        int pos = carry + s[threadIdx.x] - v;
        if (v && pos < NAG) rows[pos] = i;
        carry += s[1023];
        __syncthreads();
    }
}

// ---------------- GEMM: C[M,1024] = A[M,K] @ B[K,1024] + bias ----------------
// BM=64, BN=64, BK=16, 256 threads, 4x4 microtile. K in {16,128}.
__global__ void k_gemm(const float* __restrict__ A, const float* __restrict__ B,
                       const float* __restrict__ bias, float* __restrict__ C,
                       int M, int K) {
    __shared__ float As[16][64];
    __shared__ float Bs[16][64];
    int tid = threadIdx.x;
    int tx = tid & 15, ty = tid >> 4;
    int m0 = blockIdx.y * 64, n0 = blockIdx.x * 64;
    int lrow = tid >> 2;            // 0..63 (A tile row)
    int lc4 = (tid & 3) * 4;        // 0,4,8,12 (A tile k)
    int brow = tid >> 4;            // 0..15 (B tile k)
    int bc4 = (tid & 15) * 4;       // 0..60 (B tile col)
    float acc[4][4] = {};
    for (int k0 = 0; k0 < K; k0 += 16) {
        float4 av = make_float4(0.f, 0.f, 0.f, 0.f);
        if (m0 + lrow < M)
            av = *(const float4*)&A[(size_t)(m0 + lrow) * K + k0 + lc4];
        As[lc4 + 0][lrow] = av.x;
        As[lc4 + 1][lrow] = av.y;
        As[lc4 + 2][lrow] = av.z;
        As[lc4 + 3][lrow] = av.w;
        *(float4*)&Bs[brow][bc4] =
            *(const float4*)&B[(size_t)(k0 + brow) * 1024 + n0 + bc4];
        __syncthreads();
#pragma unroll
        for (int k = 0; k < 16; k++) {
            float4 a = *(float4*)&As[k][ty * 4];
            float4 b = *(float4*)&Bs[k][tx * 4];
            float ar[4] = {a.x, a.y, a.z, a.w};
            float br[4] = {b.x, b.y, b.z, b.w};
#pragma unroll
            for (int i = 0; i < 4; i++)
#pragma unroll
                for (int j = 0; j < 4; j++) acc[i][j] += ar[i] * br[j];
        }
        __syncthreads();
    }
    float4 bv = *(const float4*)&bias[n0 + tx * 4];
    float bb[4] = {bv.x, bv.y, bv.z, bv.w};
#pragma unroll
    for (int i = 0; i < 4; i++) {
        int m = m0 + ty * 4 + i;
        if (m < M) {
            float4 o;
            o.x = acc[i][0] + bb[0];
            o.y = acc[i][1] + bb[1];
            o.z = acc[i][2] + bb[2];
            o.w = acc[i][3] + bb[3];
            *(float4*)&C[(size_t)m * 1024 + n0 + tx * 4] = o;
        }
    }
}

// ---------------- edge attention: exp(alpha[e,h]) (softmax shift-invariant, no max needed) ----
// block per destination node; xr[dst] + att cached in SMEM; warp per edge.
__global__ void k_alpha(const float* __restrict__ xl, const float* __restrict__ xr,
                        const float* __restrict__ att,
                        const int* __restrict__ off, const int* __restrict__ csr,
                        float* __restrict__ ea) {
    int n = blockIdx.x;
    __shared__ float sxr[HC];
    __shared__ float satt[HC];
    int tid = threadIdx.x;
    for (int i = tid; i < HC; i += 256) {
        sxr[i] = xr[(size_t)n * HC + i];
        satt[i] = att[i];
    }
    __syncthreads();
    int beg = off[n], end = off[n + 1];
    int wid = tid >> 5, lane = tid & 31;
    for (int e = beg + wid; e < end; e += 8) {
        int src = csr[e];
        const float4* xls = (const float4*)&xl[(size_t)src * HC];
#pragma unroll
        for (int h = 0; h < HH; h++) {
            int c4 = h * 32 + lane;  // float4 index
            float4 a4 = xls[c4];
            float4 r4 = *(const float4*)&sxr[c4 * 4];
            float4 t4 = *(const float4*)&satt[c4 * 4];
            float z0 = a4.x + r4.x; z0 = z0 > 0.f ? z0 : 0.2f * z0;
            float z1 = a4.y + r4.y; z1 = z1 > 0.f ? z1 : 0.2f * z1;
            float z2 = a4.z + r4.z; z2 = z2 > 0.f ? z2 : 0.2f * z2;
            float z3 = a4.w + r4.w; z3 = z3 > 0.f ? z3 : 0.2f * z3;
            float s = t4.x * z0 + t4.y * z1 + t4.z * z2 + t4.w * z3;
#pragma unroll
            for (int o = 16; o; o >>= 1) s += __shfl_xor_sync(0xffffffffu, s, o);
            if (lane == 0) ea[(size_t)e * HH + h] = __expf(s);
        }
    }
}

// ---------------- aggregation: softmax-normalize, weighted sum, head-mean + bias + relu ----
__global__ void k_aggr(const float* __restrict__ xl, const float* __restrict__ ea,
                       const int* __restrict__ off, const int* __restrict__ csr,
                       const float* __restrict__ bias, float* __restrict__ out) {
    int n = blockIdx.x;
    __shared__ float den[HH];
    __shared__ float sacc[HC];
    int tid = threadIdx.x;
    int beg = off[n], end = off[n + 1];
    if (tid < HH) {
        float s = 1e-16f;
        for (int e = beg; e < end; e++) s += ea[(size_t)e * HH + tid];
        den[tid] = s;
    }
    __syncthreads();
    int h = tid >> 5, lane = tid & 31;
    float rd = 1.0f / den[h];
    float4 acc = make_float4(0.f, 0.f, 0.f, 0.f);
    for (int e = beg; e < end; e++) {
        float w = ea[(size_t)e * HH + h] * rd;
        float4 v = *(const float4*)&xl[(size_t)csr[e] * HC + h * CC + lane * 4];
        acc.x += w * v.x;
        acc.y += w * v.y;
        acc.z += w * v.z;
        acc.w += w * v.w;
    }
    *(float4*)&sacc[h * CC + lane * 4] = acc;
    __syncthreads();
    if (tid < CC) {
        float s = 0.f;
#pragma unroll
        for (int hh = 0; hh < HH; hh++) s += sacc[hh * CC + tid];
        s = s * 0.125f + bias[tid];
        if (s < 0.f) s = 0.f;  // relu (both layers)
        out[(size_t)n * CC + tid] = s;
    }
}

// ---------------- final linear on drone rows ----------------
__global__ void k_out(const float* __restrict__ h2, const float* __restrict__ W,
                      const float* __restrict__ b, const int* __restrict__ rows,
                      float* __restrict__ out) {
    int idx = blockIdx.x * blockDim.x + threadIdx.x;
    if (idx >= NAG * COUT) return;
    int r = idx >> 3, j = idx & 7;
    int node = rows[r];
    float s = b[j];
    const float* hr = &h2[(size_t)node * CC];
#pragma unroll 4
    for (int k = 0; k < CC; k++) s += hr[k] * W[k * COUT + j];
    out[idx] = s;
}

// ---------------- launch ----------------
extern "C" void kernel_launch(void* const* d_in, const int* in_sizes, int n_in,
                              void* d_out, int out_size) {
    const float* x = (const float*)d_in[0];
    const int* ei = (const int*)d_in[1];
    const float* Wl1 = (const float*)d_in[2];
    const float* bl1 = (const float*)d_in[3];
    const float* Wr1 = (const float*)d_in[4];
    const float* br1 = (const float*)d_in[5];
    const float* att1 = (const float*)d_in[6];
    const float* b1 = (const float*)d_in[7];
    const float* Wl2 = (const float*)d_in[8];
    const float* bl2 = (const float*)d_in[9];
    const float* Wr2 = (const float*)d_in[10];
    const float* br2 = (const float*)d_in[11];
    const float* att2 = (const float*)d_in[12];
    const float* b2 = (const float*)d_in[13];
    const float* Wlin = (const float*)d_in[14];
    const float* blin = (const float*)d_in[15];
    float* out = (float*)d_out;

    float *xl, *xr, *ea, *h1, *h2;
    int *deg, *wp, *off, *csr, *rows;
    cudaGetSymbolAddress((void**)&xl, g_xl);
    cudaGetSymbolAddress((void**)&xr, g_xr);
    cudaGetSymbolAddress((void**)&ea, g_ea);
    cudaGetSymbolAddress((void**)&h1, g_h1);
    cudaGetSymbolAddress((void**)&h2, g_h2);
    cudaGetSymbolAddress((void**)&deg, g_deg);
    cudaGetSymbolAddress((void**)&wp, g_wp);
    cudaGetSymbolAddress((void**)&off, g_off);
    cudaGetSymbolAddress((void**)&csr, g_csr);
    cudaGetSymbolAddress((void**)&rows, g_rows);

    const int TPB = 256;
    dim3 gGemm(1024 / 64, (NN + 63) / 64);

    // CSR build (once; shared by both layers)
    k_zero2<<<(NN + TPB - 1) / TPB, TPB>>>(deg, wp, NN);
    k_count<<<(ET + TPB - 1) / TPB, TPB>>>(ei, deg);
    k_scan<<<1, 1024>>>(deg, off);
    k_fill<<<(ET + TPB - 1) / TPB, TPB>>>(ei, off, wp, csr);
    k_rows<<<1, 1024>>>(x, rows);

    // Layer 1 (K=16)
    k_gemm<<<gGemm, TPB>>>(x, Wl1, bl1, xl, NN, 16);
    k_gemm<<<gGemm, TPB>>>(x, Wr1, br1, xr, NN, 16);
    k_alpha<<<NN, TPB>>>(xl, xr, att1, off, csr, ea);
    k_aggr<<<NN, TPB>>>(xl, ea, off, csr, b1, h1);

    // Layer 2 (K=128)
    k_gemm<<<gGemm, TPB>>>(h1, Wl2, bl2, xl, NN, 128);
    k_gemm<<<gGemm, TPB>>>(h1, Wr2, br2, xr, NN, 128);
    k_alpha<<<NN, TPB>>>(xl, xr, att2, off, csr, ea);
    k_aggr<<<NN, TPB>>>(xl, ea, off, csr, b2, h2);

    // Output projection, drone rows only
    k_out<<<(NAG * COUT + TPB - 1) / TPB, TPB>>>(h2, Wlin, blin, rows, out);
}

// round 2
// speedup vs baseline: 2.1331x; 2.1331x over previous
#include <cuda_runtime.h>
#include <cuda_bf16.h>

#define NN 10000
#define NAG 5000
#define EE 160000
#define ET 170000   /* EE + NN self-loops */
#define HH 8
#define CC 128
#define HC 1024     /* HH*CC */
#define COUT 8

// ---------------- scratch (device globals; no allocation allowed) ----------------
__device__ __align__(16) float g_xl[NN * HC];
__device__ __align__(16) float g_xr[NN * HC];
__device__ __align__(16) float g_h1[NN * CC];
__device__ __align__(16) float g_h2[NN * CC];
__device__ int g_deg[NN];
__device__ int g_wp[NN];
__device__ int g_off[NN + 1];
__device__ int g_csr[ET];
__device__ int g_rows[NAG];

// ---------------- CSR build ----------------
__global__ void k_zero2(int* a, int* b, int n) {
    int i = blockIdx.x * blockDim.x + threadIdx.x;
    if (i < n) { a[i] = 0; b[i] = 0; }
}

__global__ void k_count(const int* __restrict__ ei, int* __restrict__ deg) {
    int e = blockIdx.x * blockDim.x + threadIdx.x;
    if (e >= ET) return;
    int dst = (e < EE) ? ei[EE + e] : (e - EE);
    atomicAdd(&deg[dst], 1);
}

__global__ void k_scan(const int* __restrict__ deg, int* __restrict__ off) {
    __shared__ int s[1024];
    int carry = 0;
    for (int base = 0; base < NN; base += 1024) {
        int i = base + threadIdx.x;
        int v = (i < NN) ? deg[i] : 0;
        s[threadIdx.x] = v;
        __syncthreads();
        for (int d = 1; d < 1024; d <<= 1) {
            int t = (threadIdx.x >= d) ? s[threadIdx.x - d] : 0;
            __syncthreads();
            s[threadIdx.x] += t;
            __syncthreads();
        }
        if (i < NN) off[i] = carry + s[threadIdx.x] - v;
        carry += s[1023];
        __syncthreads();
    }
    if (threadIdx.x == 0) off[NN] = carry;
}

__global__ void k_fill(const int* __restrict__ ei, const int* __restrict__ off,
                       int* __restrict__ wp, int* __restrict__ csr) {
    int e = blockIdx.x * blockDim.x + threadIdx.x;
    if (e >= ET) return;
    int src, dst;
    if (e < EE) { src = ei[e]; dst = ei[EE + e]; }
    else        { src = e - EE; dst = src; }
    int p = off[dst] + atomicAdd(&wp[dst], 1);
    csr[p] = src;
}

// Drone row gather list
__global__ void k_rows(const float* __restrict__ x, int* __restrict__ rows) {
    __shared__ int s[1024];
    int carry = 0;
    for (int base = 0; base < NN; base += 1024) {
        int i = base + threadIdx.x;
        int v = (i < NN && x[i * 16 + 15] < 0.f) ? 1 : 0;
        s[threadIdx.x] = v;
        __syncthreads();
        for (int d = 1; d < 1024; d <<= 1) {
            int t = (threadIdx.x >= d) ? s[threadIdx.x - d] : 0;
            __syncthreads();
            s[threadIdx.x] += t;
            __syncthreads();
        }
        int pos = carry + s[threadIdx.x] - v;
        if (v && pos < NAG) rows[pos] = i;
        carry += s[1023];
        __syncthreads();
    }
}

// ---------------- GEMM: C[M,1024] = A[M,K] @ B[K,1024] + bias ----------------
// BM=128, BN=128, BK=16, 256 threads, 8x8 microtile.
__global__ __launch_bounds__(256, 2)
void k_gemm(const float* __restrict__ A, const float* __restrict__ B,
            const float* __restrict__ bias, float* __restrict__ C,
            int M, int K) {
    __shared__ float As[16][128];   // [k][m]
    __shared__ float Bs[16][128];   // [k][n]
    int tid = threadIdx.x;
    int tx = tid & 15, ty = tid >> 4;      // 16x16 thread grid, 8x8 micro
    int m0 = blockIdx.y * 128, n0 = blockIdx.x * 128;

    // A load mapping: row = tid>>1 (0..127), kb = (tid&1)*8
    int arow = tid >> 1;
    int akb = (tid & 1) * 8;
    // B load mapping: row = tid>>4 (0..15), col = (tid&15)*8
    int brow = tid >> 4;
    int bcol = (tid & 15) * 8;

    float acc[8][8] = {};

    for (int k0 = 0; k0 < K; k0 += 16) {
        // load A 128x16 (guarded), transpose into As[k][m]
        float4 a0 = make_float4(0.f, 0.f, 0.f, 0.f), a1 = a0;
        if (m0 + arow < M) {
            const float* ap = &A[(size_t)(m0 + arow) * K + k0 + akb];
            a0 = *(const float4*)(ap);
            a1 = *(const float4*)(ap + 4);
        }
        As[akb + 0][arow] = a0.x;
        As[akb + 1][arow] = a0.y;
        As[akb + 2][arow] = a0.z;
        As[akb + 3][arow] = a0.w;
        As[akb + 4][arow] = a1.x;
        As[akb + 5][arow] = a1.y;
        As[akb + 6][arow] = a1.z;
        As[akb + 7][arow] = a1.w;
        // load B 16x128
        const float* bp = &B[(size_t)(k0 + brow) * 1024 + n0 + bcol];
        *(float4*)&Bs[brow][bcol] = *(const float4*)(bp);
        *(float4*)&Bs[brow][bcol + 4] = *(const float4*)(bp + 4);
        __syncthreads();
#pragma unroll
        for (int k = 0; k < 16; k++) {
            float4 am0 = *(float4*)&As[k][ty * 8];
            float4 am1 = *(float4*)&As[k][ty * 8 + 4];
            float4 bn0 = *(float4*)&Bs[k][tx * 8];
            float4 bn1 = *(float4*)&Bs[k][tx * 8 + 4];
            float ar[8] = {am0.x, am0.y, am0.z, am0.w, am1.x, am1.y, am1.z, am1.w};
            float br[8] = {bn0.x, bn0.y, bn0.z, bn0.w, bn1.x, bn1.y, bn1.z, bn1.w};
#pragma unroll
            for (int i = 0; i < 8; i++)
#pragma unroll
                for (int j = 0; j < 8; j++) acc[i][j] += ar[i] * br[j];
        }
        __syncthreads();
    }

    float4 bv0 = *(const float4*)&bias[n0 + tx * 8];
    float4 bv1 = *(const float4*)&bias[n0 + tx * 8 + 4];
    float bb[8] = {bv0.x, bv0.y, bv0.z, bv0.w, bv1.x, bv1.y, bv1.z, bv1.w};
#pragma unroll
    for (int i = 0; i < 8; i++) {
        int m = m0 + ty * 8 + i;
        if (m < M) {
            float4 o0, o1;
            o0.x = acc[i][0] + bb[0];
            o0.y = acc[i][1] + bb[1];
            o0.z = acc[i][2] + bb[2];
            o0.w = acc[i][3] + bb[3];
            o1.x = acc[i][4] + bb[4];
            o1.y = acc[i][5] + bb[5];
            o1.z = acc[i][6] + bb[6];
            o1.w = acc[i][7] + bb[7];
            float* cp = &C[(size_t)m * 1024 + n0 + tx * 8];
            *(float4*)(cp) = o0;
            *(float4*)(cp + 4) = o1;
        }
    }
}

// ---------------- fused edge attention + softmax + aggregation ----------------
// block per destination node; warp h owns head h. Single pass over edges:
// w = exp(att_h . leaky(xl[src,h,:] + xr[dst,h,:])); acc += w*xl[src,h,:]; den += w.
__global__ __launch_bounds__(256)
void k_edge(const float* __restrict__ xl, const float* __restrict__ xr,
            const float* __restrict__ att,
            const int* __restrict__ off, const int* __restrict__ csr,
            const float* __restrict__ bias, float* __restrict__ out) {
    int n = blockIdx.x;
    int tid = threadIdx.x, h = tid >> 5, lane = tid & 31;
    __shared__ float sacc[HC];
    int base = h * CC + lane * 4;
    float4 r4 = *(const float4*)&xr[(size_t)n * HC + base];
    float4 t4 = *(const float4*)&att[base];
    int beg = off[n], end = off[n + 1];
    float4 acc = make_float4(0.f, 0.f, 0.f, 0.f);
    float den = 1e-16f;
    for (int e = beg; e < end; e++) {
        int src = csr[e];
        float4 v4 = *(const float4*)&xl[(size_t)src * HC + base];
        float z0 = v4.x + r4.x; z0 = z0 > 0.f ? z0 : 0.2f * z0;
        float z1 = v4.y + r4.y; z1 = z1 > 0.f ? z1 : 0.2f * z1;
        float z2 = v4.z + r4.z; z2 = z2 > 0.f ? z2 : 0.2f * z2;
        float z3 = v4.w + r4.w; z3 = z3 > 0.f ? z3 : 0.2f * z3;
        float s = t4.x * z0 + t4.y * z1 + t4.z * z2 + t4.w * z3;
#pragma unroll
        for (int o = 16; o; o >>= 1) s += __shfl_xor_sync(0xffffffffu, s, o);
        float w = __expf(s);
        acc.x += w * v4.x;
        acc.y += w * v4.y;
        acc.z += w * v4.z;
        acc.w += w * v4.w;
        den += w;
    }
    float rd = 1.0f / den;
    acc.x *= rd; acc.y *= rd; acc.z *= rd; acc.w *= rd;
    *(float4*)&sacc[base] = acc;
    __syncthreads();
    if (tid < CC) {
        float s = 0.f;
#pragma unroll
        for (int hh = 0; hh < HH; hh++) s += sacc[hh * CC + tid];
        s = s * 0.125f + bias[tid];
        if (s < 0.f) s = 0.f;  // relu (applied after both layers)
        out[(size_t)n * CC + tid] = s;
    }
}

// ---------------- final linear on drone rows ----------------
__global__ void k_out(const float* __restrict__ h2, const float* __restrict__ W,
                      const float* __restrict__ b, const int* __restrict__ rows,
                      float* __restrict__ out) {
    int idx = blockIdx.x * blockDim.x + threadIdx.x;
    if (idx >= NAG * COUT) return;
    int r = idx >> 3, j = idx & 7;
    int node = rows[r];
    float s = b[j];
    const float* hr = &h2[(size_t)node * CC];
#pragma unroll 4
    for (int k = 0; k < CC; k++) s += hr[k] * W[k * COUT + j];
    out[idx] = s;
}

// ---------------- launch ----------------
extern "C" void kernel_launch(void* const* d_in, const int* in_sizes, int n_in,
                              void* d_out, int out_size) {
    const float* x = (const float*)d_in[0];
    const int* ei = (const int*)d_in[1];
    const float* Wl1 = (const float*)d_in[2];
    const float* bl1 = (const float*)d_in[3];
    const float* Wr1 = (const float*)d_in[4];
    const float* br1 = (const float*)d_in[5];
    const float* att1 = (const float*)d_in[6];
    const float* b1 = (const float*)d_in[7];
    const float* Wl2 = (const float*)d_in[8];
    const float* bl2 = (const float*)d_in[9];
    const float* Wr2 = (const float*)d_in[10];
    const float* br2 = (const float*)d_in[11];
    const float* att2 = (const float*)d_in[12];
    const float* b2 = (const float*)d_in[13];
    const float* Wlin = (const float*)d_in[14];
    const float* blin = (const float*)d_in[15];
    float* out = (float*)d_out;

    float *xl, *xr, *h1, *h2;
    int *deg, *wp, *off, *csr, *rows;
    cudaGetSymbolAddress((void**)&xl, g_xl);
    cudaGetSymbolAddress((void**)&xr, g_xr);
    cudaGetSymbolAddress((void**)&h1, g_h1);
    cudaGetSymbolAddress((void**)&h2, g_h2);
    cudaGetSymbolAddress((void**)&deg, g_deg);
    cudaGetSymbolAddress((void**)&wp, g_wp);
    cudaGetSymbolAddress((void**)&off, g_off);
    cudaGetSymbolAddress((void**)&csr, g_csr);
    cudaGetSymbolAddress((void**)&rows, g_rows);

    const int TPB = 256;
    dim3 gGemm(1024 / 128, (NN + 127) / 128);

    // CSR build (shared by both layers)
    k_zero2<<<(NN + TPB - 1) / TPB, TPB>>>(deg, wp, NN);
    k_count<<<(ET + TPB - 1) / TPB, TPB>>>(ei, deg);
    k_scan<<<1, 1024>>>(deg, off);
    k_fill<<<(ET + TPB - 1) / TPB, TPB>>>(ei, off, wp, csr);
    k_rows<<<1, 1024>>>(x, rows);

    // Layer 1 (K=16)
    k_gemm<<<gGemm, TPB>>>(x, Wl1, bl1, xl, NN, 16);
    k_gemm<<<gGemm, TPB>>>(x, Wr1, br1, xr, NN, 16);
    k_edge<<<NN, TPB>>>(xl, xr, att1, off, csr, b1, h1);

    // Layer 2 (K=128)
    k_gemm<<<gGemm, TPB>>>(h1, Wl2, bl2, xl, NN, 128);
    k_gemm<<<gGemm, TPB>>>(h1, Wr2, br2, xr, NN, 128);
    k_edge<<<NN, TPB>>>(xl, xr, att2, off, csr, b2, h2);

    // Output projection, drone rows only
    k_out<<<(NAG * COUT + TPB - 1) / TPB, TPB>>>(h2, Wlin, blin, rows, out);
}

// round 3
// speedup vs baseline: 2.4100x; 1.1298x over previous
#include <cuda_runtime.h>
#include <cuda_bf16.h>
#include <mma.h>
using namespace nvcuda;

#define NN 10000
#define NP 10112    /* padded to 79*128 for unguarded wmma stores */
#define NAG 5000
#define EE 160000
#define ET 170000   /* EE + NN self-loops */
#define HH 8
#define CC 128
#define HC 1024     /* HH*CC */
#define COUT 8

// ---------------- scratch (device globals; no allocation allowed) ----------------
__device__ __align__(16) float g_xl[NP * HC];
__device__ __align__(16) float g_xr[NP * HC];
__device__ __align__(16) float g_h1[NP * CC];   // pad rows stay zero (.bss), never written/read
__device__ __align__(16) float g_h2[NP * CC];
__device__ int g_deg[NN];
__device__ int g_wp[NN];
__device__ int g_off[NN + 1];
__device__ int g_csr[ET];
__device__ int g_rows[NAG];

// ---------------- CSR build ----------------
__global__ void k_zero2(int* a, int* b, int n) {
    int i = blockIdx.x * blockDim.x + threadIdx.x;
    if (i < n) { a[i] = 0; b[i] = 0; }
}

__global__ void k_count(const int* __restrict__ ei, int* __restrict__ deg) {
    int e = blockIdx.x * blockDim.x + threadIdx.x;
    if (e >= ET) return;
    int dst = (e < EE) ? ei[EE + e] : (e - EE);
    atomicAdd(&deg[dst], 1);
}

__global__ void k_scan(const int* __restrict__ deg, int* __restrict__ off) {
    __shared__ int s[1024];
    int carry = 0;
    for (int base = 0; base < NN; base += 1024) {
        int i = base + threadIdx.x;
        int v = (i < NN) ? deg[i] : 0;
        s[threadIdx.x] = v;
        __syncthreads();
        for (int d = 1; d < 1024; d <<= 1) {
            int t = (threadIdx.x >= d) ? s[threadIdx.x - d] : 0;
            __syncthreads();
            s[threadIdx.x] += t;
            __syncthreads();
        }
        if (i < NN) off[i] = carry + s[threadIdx.x] - v;
        carry += s[1023];
        __syncthreads();
    }
    if (threadIdx.x == 0) off[NN] = carry;
}

__global__ void k_fill(const int* __restrict__ ei, const int* __restrict__ off,
                       int* __restrict__ wp, int* __restrict__ csr) {
    int e = blockIdx.x * blockDim.x + threadIdx.x;
    if (e >= ET) return;
    int src, dst;
    if (e < EE) { src = ei[e]; dst = ei[EE + e]; }
    else        { src = e - EE; dst = src; }
    int p = off[dst] + atomicAdd(&wp[dst], 1);
    csr[p] = src;
}

__global__ void k_rows(const float* __restrict__ x, int* __restrict__ rows) {
    __shared__ int s[1024];
    int carry = 0;
    for (int base = 0; base < NN; base += 1024) {
        int i = base + threadIdx.x;
        int v = (i < NN && x[i * 16 + 15] < 0.f) ? 1 : 0;
        s[threadIdx.x] = v;
        __syncthreads();
        for (int d = 1; d < 1024; d <<= 1) {
            int t = (threadIdx.x >= d) ? s[threadIdx.x - d] : 0;
            __syncthreads();
            s[threadIdx.x] += t;
            __syncthreads();
        }
        int pos = carry + s[threadIdx.x] - v;
        if (v && pos < NAG) rows[pos] = i;
        carry += s[1023];
        __syncthreads();
    }
}

// ---------------- TF32 tensor-core GEMM: C[NP,1024] = A[M,K] @ B[K,1024] + bias ----
// BM=128, BN=128, BK=16. 8 warps, each 64x32 (4x2 wmma m16n16k8 frags).
// C rows are padded (NP) so stores are unguarded; A loads guarded by M.
#define ALD 20      /* As leading dim (16 + 4 pad) */
#define BLD 132     /* Bs leading dim (128 + 4 pad) */
__global__ __launch_bounds__(256)
void k_gemm_tf32(const float* __restrict__ A, const float* __restrict__ B,
                 const float* __restrict__ bias, float* __restrict__ C,
                 int M, int K) {
    __shared__ float sh[8192];           // 32KB: As(2560) + Bs(2112) during mainloop; staging in epilogue
    float* shA = sh;                     // [128][ALD]
    float* shB = sh + 128 * ALD;         // [16][BLD]

    int tid = threadIdx.x;
    int wid = tid >> 5, lane = tid & 31;
    int wm = wid >> 2, wn = wid & 3;     // 2x4 warp grid
    int m0 = blockIdx.y * 128, n0 = blockIdx.x * 128;

    int arow = tid >> 1;                 // 0..127
    int akb = (tid & 1) * 8;             // 0 or 8
    int brow = tid >> 4;                 // 0..15
    int bcol = (tid & 15) * 8;           // 0..120

    wmma::fragment<wmma::accumulator, 16, 16, 8, float> acc[4][2];
#pragma unroll
    for (int i = 0; i < 4; i++)
#pragma unroll
        for (int j = 0; j < 2; j++) wmma::fill_fragment(acc[i][j], 0.f);

    for (int k0 = 0; k0 < K; k0 += 16) {
        // load A tile 128x16 (guarded rows)
        float4 a0 = make_float4(0.f, 0.f, 0.f, 0.f), a1 = a0;
        if (m0 + arow < M) {
            const float* ap = &A[(size_t)(m0 + arow) * K + k0 + akb];
            a0 = *(const float4*)(ap);
            a1 = *(const float4*)(ap + 4);
        }
        *(float4*)&shA[arow * ALD + akb] = a0;
        *(float4*)&shA[arow * ALD + akb + 4] = a1;
        // load B tile 16x128
        const float* bp = &B[(size_t)(k0 + brow) * 1024 + n0 + bcol];
        *(float4*)&shB[brow * BLD + bcol] = *(const float4*)(bp);
        *(float4*)&shB[brow * BLD + bcol + 4] = *(const float4*)(bp + 4);
        __syncthreads();

#pragma unroll
        for (int kk = 0; kk < 16; kk += 8) {
            wmma::fragment<wmma::matrix_a, 16, 16, 8, wmma::precision::tf32, wmma::row_major> af[4];
            wmma::fragment<wmma::matrix_b, 16, 16, 8, wmma::precision::tf32, wmma::row_major> bf[2];
#pragma unroll
            for (int i = 0; i < 4; i++) {
                wmma::load_matrix_sync(af[i], &shA[(wm * 64 + i * 16) * ALD + kk], ALD);
#pragma unroll
                for (int t = 0; t < af[i].num_elements; t++)
                    af[i].x[t] = wmma::__float_to_tf32(af[i].x[t]);
            }
#pragma unroll
            for (int j = 0; j < 2; j++) {
                wmma::load_matrix_sync(bf[j], &shB[kk * BLD + wn * 32 + j * 16], BLD);
#pragma unroll
                for (int t = 0; t < bf[j].num_elements; t++)
                    bf[j].x[t] = wmma::__float_to_tf32(bf[j].x[t]);
            }
#pragma unroll
            for (int i = 0; i < 4; i++)
#pragma unroll
                for (int j = 0; j < 2; j++)
                    wmma::mma_sync(acc[i][j], af[i], bf[j], acc[i][j]);
        }
        __syncthreads();
    }

    // epilogue: stage 64x16 per warp, add bias, vectorized store (rows padded -> no guard)
    float* stage = sh + wid * 1024;      // 64 rows x 16 cols per warp
#pragma unroll
    for (int j = 0; j < 2; j++) {
        if (j == 0) __syncthreads();     // shA/shB dead for all warps before overwrite
#pragma unroll
        for (int i = 0; i < 4; i++)
            wmma::store_matrix_sync(&stage[i * 256], acc[i][j], 16, wmma::mem_row_major);
        __syncwarp();
        int row0 = m0 + wm * 64;
        int col0 = n0 + wn * 32 + j * 16;
#pragma unroll
        for (int it = 0; it < 8; it++) {
            int f = it * 128 + lane * 4;
            int r = f >> 4, c = f & 15;
            float4 v = *(float4*)&stage[f];
            float4 bv = *(const float4*)&bias[col0 + c];
            v.x += bv.x; v.y += bv.y; v.z += bv.z; v.w += bv.w;
            *(float4*)&C[(size_t)(row0 + r) * 1024 + col0 + c] = v;
        }
        __syncwarp();
    }
}

// ---------------- fused edge attention + softmax + aggregation ----------------
__device__ __forceinline__ float dot_leaky(float4 v, float4 r, float4 t) {
    float z0 = v.x + r.x; z0 = z0 > 0.f ? z0 : 0.2f * z0;
    float z1 = v.y + r.y; z1 = z1 > 0.f ? z1 : 0.2f * z1;
    float z2 = v.z + r.z; z2 = z2 > 0.f ? z2 : 0.2f * z2;
    float z3 = v.w + r.w; z3 = z3 > 0.f ? z3 : 0.2f * z3;
    return t.x * z0 + t.y * z1 + t.z * z2 + t.w * z3;
}

__global__ __launch_bounds__(256)
void k_edge(const float* __restrict__ xl, const float* __restrict__ xr,
            const float* __restrict__ att,
            const int* __restrict__ off, const int* __restrict__ csr,
            const float* __restrict__ bias, float* __restrict__ out) {
    int n = blockIdx.x;
    int tid = threadIdx.x, h = tid >> 5, lane = tid & 31;
    __shared__ float sacc[HC];
    int base = h * CC + lane * 4;
    float4 r4 = *(const float4*)&xr[(size_t)n * HC + base];
    float4 t4 = *(const float4*)&att[base];
    int beg = off[n], end = off[n + 1];
    float4 acc = make_float4(0.f, 0.f, 0.f, 0.f);
    float den = 1e-16f;
    int e = beg;
    for (; e + 2 <= end; e += 2) {
        int s0 = csr[e], s1 = csr[e + 1];
        float4 u4 = *(const float4*)&xl[(size_t)s0 * HC + base];
        float4 v4 = *(const float4*)&xl[(size_t)s1 * HC + base];
        float a = dot_leaky(u4, r4, t4);
        float b = dot_leaky(v4, r4, t4);
#pragma unroll
        for (int o = 16; o; o >>= 1) {
            a += __shfl_xor_sync(0xffffffffu, a, o);
            b += __shfl_xor_sync(0xffffffffu, b, o);
        }
        float wa = __expf(a), wb = __expf(b);
        acc.x += wa * u4.x + wb * v4.x;
        acc.y += wa * u4.y + wb * v4.y;
        acc.z += wa * u4.z + wb * v4.z;
        acc.w += wa * u4.w + wb * v4.w;
        den += wa + wb;
    }
    if (e < end) {
        int s0 = csr[e];
        float4 u4 = *(const float4*)&xl[(size_t)s0 * HC + base];
        float a = dot_leaky(u4, r4, t4);
#pragma unroll
        for (int o = 16; o; o >>= 1) a += __shfl_xor_sync(0xffffffffu, a, o);
        float wa = __expf(a);
        acc.x += wa * u4.x;
        acc.y += wa * u4.y;
        acc.z += wa * u4.z;
        acc.w += wa * u4.w;
        den += wa;
    }
    float rd = 1.0f / den;
    acc.x *= rd; acc.y *= rd; acc.z *= rd; acc.w *= rd;
    *(float4*)&sacc[base] = acc;
    __syncthreads();
    if (tid < CC) {
        float s = 0.f;
#pragma unroll
        for (int hh = 0; hh < HH; hh++) s += sacc[hh * CC + tid];
        s = s * 0.125f + bias[tid];
        if (s < 0.f) s = 0.f;
        out[(size_t)n * CC + tid] = s;
    }
}

// ---------------- final linear on drone rows ----------------
__global__ void k_out(const float* __restrict__ h2, const float* __restrict__ W,
                      const float* __restrict__ b, const int* __restrict__ rows,
                      float* __restrict__ out) {
    int idx = blockIdx.x * blockDim.x + threadIdx.x;
    if (idx >= NAG * COUT) return;
    int r = idx >> 3, j = idx & 7;
    int node = rows[r];
    float s = b[j];
    const float* hr = &h2[(size_t)node * CC];
#pragma unroll 4
    for (int k = 0; k < CC; k++) s += hr[k] * W[k * COUT + j];
    out[idx] = s;
}

// ---------------- launch ----------------
extern "C" void kernel_launch(void* const* d_in, const int* in_sizes, int n_in,
                              void* d_out, int out_size) {
    const float* x = (const float*)d_in[0];
    const int* ei = (const int*)d_in[1];
    const float* Wl1 = (const float*)d_in[2];
    const float* bl1 = (const float*)d_in[3];
    const float* Wr1 = (const float*)d_in[4];
    const float* br1 = (const float*)d_in[5];
    const float* att1 = (const float*)d_in[6];
    const float* b1 = (const float*)d_in[7];
    const float* Wl2 = (const float*)d_in[8];
    const float* bl2 = (const float*)d_in[9];
    const float* Wr2 = (const float*)d_in[10];
    const float* br2 = (const float*)d_in[11];
    const float* att2 = (const float*)d_in[12];
    const float* b2 = (const float*)d_in[13];
    const float* Wlin = (const float*)d_in[14];
    const float* blin = (const float*)d_in[15];
    float* out = (float*)d_out;

    float *xl, *xr, *h1, *h2;
    int *deg, *wp, *off, *csr, *rows;
    cudaGetSymbolAddress((void**)&xl, g_xl);
    cudaGetSymbolAddress((void**)&xr, g_xr);
    cudaGetSymbolAddress((void**)&h1, g_h1);
    cudaGetSymbolAddress((void**)&h2, g_h2);
    cudaGetSymbolAddress((void**)&deg, g_deg);
    cudaGetSymbolAddress((void**)&wp, g_wp);
    cudaGetSymbolAddress((void**)&off, g_off);
    cudaGetSymbolAddress((void**)&csr, g_csr);
    cudaGetSymbolAddress((void**)&rows, g_rows);

    const int TPB = 256;
    dim3 gGemm(1024 / 128, NP / 128);   // 8 x 79

    // CSR build (shared by both layers)
    k_zero2<<<(NN + TPB - 1) / TPB, TPB>>>(deg, wp, NN);
    k_count<<<(ET + TPB - 1) / TPB, TPB>>>(ei, deg);
    k_scan<<<1, 1024>>>(deg, off);
    k_fill<<<(ET + TPB - 1) / TPB, TPB>>>(ei, off, wp, csr);
    k_rows<<<1, 1024>>>(x, rows);

    // Layer 1 (K=16; A = harness input x, guard rows at NN)
    k_gemm_tf32<<<gGemm, TPB>>>(x, Wl1, bl1, xl, NN, 16);
    k_gemm_tf32<<<gGemm, TPB>>>(x, Wr1, br1, xr, NN, 16);
    k_edge<<<NN, TPB>>>(xl, xr, att1, off, csr, b1, h1);

    // Layer 2 (K=128; A = padded h1, pad rows are zeros)
    k_gemm_tf32<<<gGemm, TPB>>>(h1, Wl2, bl2, xl, NP, 128);
    k_gemm_tf32<<<gGemm, TPB>>>(h1, Wr2, br2, xr, NP, 128);
    k_edge<<<NN, TPB>>>(xl, xr, att2, off, csr, b2, h2);

    // Output projection, drone rows only
    k_out<<<(NAG * COUT + TPB - 1) / TPB, TPB>>>(h2, Wlin, blin, rows, out);
}